// round 13
// baseline (speedup 1.0000x reference)
#include <cuda_runtime.h>
#include <cuda_fp16.h>
#include <cstdint>

#define NODES 100000
#define NGR   1000
#define HD    128
#define NEDGE 1600000

// ---------------- scratch (activations fp16; fp32 accumulate) ----------------
__device__ __half g_h0x[NODES * HD];    // h0 fp16
__device__ __half g_hx[NODES * HD];     // current h fp16
__device__ __half g_asum[NODES * HD];   // self + neighbor sum, fp16
__device__ float g_pooled[NGR * HD];
__device__ int   g_rowptr[NODES + 1];
__device__ int   g_cursor[NODES];
__device__ int   g_csr[NEDGE];
__device__ int   g_bsums[512];
__device__ __half g_wfmt[9 * 16384];    // 9 mats x Wt[n][k] fp16

// ---------------- ptx helpers ----------------
__device__ __forceinline__ uint32_t smem_u32(const void* p) {
    uint32_t a;
    asm("{ .reg .u64 t; cvta.to.shared.u64 t, %1; cvt.u32.u64 %0, t; }" : "=r"(a) : "l"(p));
    return a;
}
__device__ __forceinline__ void ldsm4(uint32_t* r, uint32_t a) {
    asm volatile("ldmatrix.sync.aligned.m8n8.x4.shared.b16 {%0,%1,%2,%3}, [%4];"
                 : "=r"(r[0]), "=r"(r[1]), "=r"(r[2]), "=r"(r[3]) : "r"(a));
}
__device__ __forceinline__ void cpasync16(uint32_t dst, const void* src) {
    asm volatile("cp.async.cg.shared.global [%0], [%1], 16;" :: "r"(dst), "l"(src));
}
#define MMA_F16(ac, af, b0, b1)                                                     \
    asm volatile(                                                                   \
        "mma.sync.aligned.m16n8k16.row.col.f32.f16.f16.f32 "                        \
        "{%0,%1,%2,%3}, {%4,%5,%6,%7}, {%8,%9}, {%0,%1,%2,%3};"                     \
        : "+f"((ac)[0]), "+f"((ac)[1]), "+f"((ac)[2]), "+f"((ac)[3])                \
        : "r"((af)[0]), "r"((af)[1]), "r"((af)[2]), "r"((af)[3]), "r"(b0), "r"(b1))

__device__ __forceinline__ void split_f16(float4 g, uint2& uh, uint2& ul) {
    __half2 h01 = __floats2half2_rn(g.x, g.y);
    __half2 h23 = __floats2half2_rn(g.z, g.w);
    float lx = g.x - __half2float(__low2half(h01));
    float ly = g.y - __half2float(__high2half(h01));
    float lz = g.z - __half2float(__low2half(h23));
    float lw = g.w - __half2float(__high2half(h23));
    __half2 l01 = __floats2half2_rn(lx, ly);
    __half2 l23 = __floats2half2_rn(lz, lw);
    uh.x = *(uint32_t*)&h01; uh.y = *(uint32_t*)&h23;
    ul.x = *(uint32_t*)&l01; ul.y = *(uint32_t*)&l23;
}
__device__ __forceinline__ void split_f16_pair(float a, float b, uint32_t& hi, uint32_t& lo) {
    __half2 h = __floats2half2_rn(a, b);
    float la = a - __half2float(__low2half(h));
    float lb = b - __half2float(__high2half(h));
    __half2 l = __floats2half2_rn(la, lb);
    hi = *(uint32_t*)&h;
    lo = *(uint32_t*)&l;
}
__device__ __forceinline__ float4 h4_to_f4(uint2 v) {
    float2 fa = __half22float2(*(__half2*)&v.x);
    float2 fb = __half22float2(*(__half2*)&v.y);
    return make_float4(fa.x, fa.y, fb.x, fb.y);
}

// ---------------- weight pre-format ----------------
__global__ void wfmt_kernel(const float* __restrict__ W0, const float* __restrict__ W1,
                            const float* __restrict__ W2, __half* __restrict__ out) {
    int mat = blockIdx.x;
    int chunk = blockIdx.y;
    const float* W = (mat == 0) ? W0 : (mat <= 4 ? W1 + (mat - 1) * HD * HD
                                                 : W2 + (mat - 5) * HD * HD);
    __half* o = out + (size_t)mat * 16384;
    int base = chunk * 1024;
    for (int i = threadIdx.x; i < 1024; i += blockDim.x) {
        int id = base + i;
        int k = id >> 7, n = id & 127;
        o[n * HD + k] = __float2half(W[id]);
    }
}

// ---------------- utility ----------------
__global__ void zero_int_kernel(int* p, int n) {
    int i = blockIdx.x * blockDim.x + threadIdx.x;
    if (i < n) p[i] = 0;
}
__global__ void zero_float_kernel(float* p, int n) {
    int i = blockIdx.x * blockDim.x + threadIdx.x;
    if (i < n) p[i] = 0.0f;
}

// ---------------- CSR build ----------------
__global__ void hist_kernel(const int* __restrict__ ei, int* __restrict__ deg, int E) {
    int e = blockIdx.x * blockDim.x + threadIdx.x;
    if (e < E) atomicAdd(&deg[ei[E + e]], 1);
}
__global__ void scan_blocks_kernel(int* __restrict__ data, int* __restrict__ bsums, int n) {
    int tid = threadIdx.x;
    int i = blockIdx.x * 256 + tid;
    int v = (i < n) ? data[i] : 0;
    int x = v;
#pragma unroll
    for (int o = 1; o < 32; o <<= 1) {
        int y = __shfl_up_sync(0xffffffffu, x, o);
        if ((tid & 31) >= o) x += y;
    }
    __shared__ int ws[8];
    if ((tid & 31) == 31) ws[tid >> 5] = x;
    __syncthreads();
    if (tid == 0) {
        int run = 0;
#pragma unroll
        for (int w = 0; w < 8; w++) { int t = ws[w]; ws[w] = run; run += t; }
    }
    __syncthreads();
    int incl = x + ws[tid >> 5];
    if (i < n) data[i] = incl - v;
    if (tid == 255) bsums[blockIdx.x] = incl;
}
__global__ void scan_bsums_kernel(int* bsums, int nb) {
    int tid = threadIdx.x;
    int v = (tid < nb) ? bsums[tid] : 0;
    int x = v;
#pragma unroll
    for (int o = 1; o < 32; o <<= 1) {
        int y = __shfl_up_sync(0xffffffffu, x, o);
        if ((tid & 31) >= o) x += y;
    }
    __shared__ int ws[16];
    if ((tid & 31) == 31) ws[tid >> 5] = x;
    __syncthreads();
    if (tid == 0) {
        int run = 0;
#pragma unroll
        for (int w = 0; w < 16; w++) { int t = ws[w]; ws[w] = run; run += t; }
    }
    __syncthreads();
    int incl = x + ws[tid >> 5];
    if (tid < nb) bsums[tid] = incl - v;
}
__global__ void scan_finish_kernel(int* __restrict__ rowptr, const int* __restrict__ bsums,
                                   int* __restrict__ cursor, int n, int E) {
    int i = blockIdx.x * 256 + threadIdx.x;
    if (i < n) {
        int v = rowptr[i] + bsums[blockIdx.x];
        rowptr[i] = v;
        cursor[i] = v;
    }
    if (i == 0) rowptr[n] = E;
}
__global__ void fill_csr_kernel(const int* __restrict__ ei, int* __restrict__ cursor,
                                int* __restrict__ csr, int E) {
    int e = blockIdx.x * blockDim.x + threadIdx.x;
    if (e < E) {
        int s = ei[e];
        int d = ei[E + e];
        int p = atomicAdd(&cursor[d], 1);
        csr[p] = s;
    }
}

// ---------------- aggregation: asum = h[node] + sum_j h[j]  (fp32 acc, fp16 out) --------------
__global__ void agg_kernel(const int* __restrict__ rp, const int* __restrict__ cs,
                           const __half* __restrict__ h16, __half* __restrict__ asum16) {
    int gw = (blockIdx.x * blockDim.x + threadIdx.x) >> 5;
    int lane = threadIdx.x & 31;
    if (gw >= NODES) return;
    int s = rp[gw], e = rp[gw + 1];
    const uint2* h2 = (const uint2*)h16;
    float4 acc = h4_to_f4(__ldg(&h2[(size_t)gw * 32 + lane]));   // self term
    int i = s;
    for (; i + 3 < e; i += 4) {
        int u0 = cs[i], u1 = cs[i + 1], u2 = cs[i + 2], u3 = cs[i + 3];
        float4 v0 = h4_to_f4(__ldg(&h2[(size_t)u0 * 32 + lane]));
        float4 v1 = h4_to_f4(__ldg(&h2[(size_t)u1 * 32 + lane]));
        float4 v2 = h4_to_f4(__ldg(&h2[(size_t)u2 * 32 + lane]));
        float4 v3 = h4_to_f4(__ldg(&h2[(size_t)u3 * 32 + lane]));
        acc.x += (v0.x + v1.x) + (v2.x + v3.x);
        acc.y += (v0.y + v1.y) + (v2.y + v3.y);
        acc.z += (v0.z + v1.z) + (v2.z + v3.z);
        acc.w += (v0.w + v1.w) + (v2.w + v3.w);
    }
    for (; i < e; i++) {
        int u = cs[i];
        float4 v = h4_to_f4(__ldg(&h2[(size_t)u * 32 + lane]));
        acc.x += v.x; acc.y += v.y; acc.z += v.z; acc.w += v.w;
    }
    __half2 p01 = __floats2half2_rn(acc.x, acc.y);
    __half2 p23 = __floats2half2_rn(acc.z, acc.w);
    uint2 o;
    o.x = *(uint32_t*)&p01;
    o.y = *(uint32_t*)&p23;
    ((uint2*)asum16)[(size_t)gw * 32 + lane] = o;
}

// ---------------- GEMM tile machinery: 128 rows/CTA, 256 threads (4M x 2N warps) --------------
#define PITCH 136
#define OFF_AH 0
#define OFF_AL (128 * PITCH * 2)            // 34816
#define OFF_B  (2 * 128 * PITCH * 2)        // 69632
#define SM_TOT (OFF_B + 128 * PITCH * 2)    // 104448 -> 2 CTAs/SM

__device__ __forceinline__ void stage_W(uint32_t sb, const __half* Wfmt, int tid) {
    const float4* src = (const float4*)Wfmt;
#pragma unroll
    for (int i = 0; i < 8; i++) {
        int id = tid + i * 256;             // 2048 float4
        int n = id >> 4, c = id & 15;
        cpasync16(sb + OFF_B + n * (PITCH * 2) + c * 16, src + id);
    }
    asm volatile("cp.async.commit_group;" ::: "memory");
}

__device__ __forceinline__ void mainloop(uint32_t sb, uint32_t aoff0, uint32_t aoff1,
                                         uint32_t boff, float acc[2][8][4]) {
#pragma unroll
    for (int ks = 0; ks < 8; ks++) {
        uint32_t kb = ks * 32;
        uint32_t ah[2][4], al[2][4], b[4][4];
        ldsm4(ah[0], sb + OFF_AH + aoff0 + kb);
        ldsm4(ah[1], sb + OFF_AH + aoff1 + kb);
        ldsm4(al[0], sb + OFF_AL + aoff0 + kb);
        ldsm4(al[1], sb + OFF_AL + aoff1 + kb);
#pragma unroll
        for (int nt = 0; nt < 4; nt++)
            ldsm4(b[nt], sb + OFF_B + boff + nt * 16 * (PITCH * 2) + kb);
#pragma unroll
        for (int mi = 0; mi < 2; mi++)
#pragma unroll
            for (int nt = 0; nt < 4; nt++) {
                MMA_F16(acc[mi][2 * nt],     ah[mi], b[nt][0], b[nt][1]);
                MMA_F16(acc[mi][2 * nt],     al[mi], b[nt][0], b[nt][1]);
                MMA_F16(acc[mi][2 * nt + 1], ah[mi], b[nt][2], b[nt][3]);
                MMA_F16(acc[mi][2 * nt + 1], al[mi], b[nt][2], b[nt][3]);
            }
    }
}

// ---------------- GEMM0: C16 = fp16(relu(x @ W + b)), x fp32 ----------------
__global__ __launch_bounds__(256, 2) void tgemm_kernel(
    const float* __restrict__ A, const __half* __restrict__ Wfmt,
    const float* __restrict__ bias, __half* __restrict__ C16) {
    extern __shared__ char sm[];
    uint32_t sb = smem_u32(sm);
    int tid = threadIdx.x;
    int lane = tid & 31, wid = tid >> 5;
    int bm = blockIdx.x * 128;

    stage_W(sb, Wfmt, tid);
    {
        const float4* Ap = (const float4*)A;
#pragma unroll
        for (int i = 0; i < 16; i++) {
            int id4 = tid + i * 256;        // 4096 float4 = 128 rows x 32
            int m = id4 >> 5, k4 = id4 & 31;
            int gr = bm + m;
            if (gr >= NODES) gr = NODES - 1;
            float4 g = Ap[(size_t)gr * 32 + k4];
            uint2 uh, ul;
            split_f16(g, uh, ul);
            int db = m * (PITCH * 2) + k4 * 8;
            *(uint2*)(sm + OFF_AH + db) = uh;
            *(uint2*)(sm + OFF_AL + db) = ul;
        }
    }
    asm volatile("cp.async.wait_group 0;" ::: "memory");
    __syncthreads();

    int mwarp = wid & 3, nwarp = wid >> 2;
    int m0 = mwarp * 32, n0 = nwarp * 64;
    uint32_t arow = (lane & 7) + ((lane >> 3) & 1) * 8;
    uint32_t acol = (lane >> 4) * 8;
    uint32_t aoff0 = ((m0 + arow) * PITCH + acol) * 2;
    uint32_t aoff1 = ((m0 + 16 + arow) * PITCH + acol) * 2;
    uint32_t boff = ((n0 + (lane & 7) + (lane >> 4) * 8) * PITCH + ((lane >> 3) & 1) * 8) * 2;

    float acc[2][8][4];
#pragma unroll
    for (int mi = 0; mi < 2; mi++)
#pragma unroll
        for (int t = 0; t < 8; t++)
#pragma unroll
            for (int j = 0; j < 4; j++) acc[mi][t][j] = 0.0f;

    mainloop(sb, aoff0, aoff1, boff, acc);

    int c2 = (lane & 3) * 2;
#pragma unroll
    for (int mi = 0; mi < 2; mi++) {
        int r = bm + m0 + mi * 16 + (lane >> 2);
#pragma unroll
        for (int t = 0; t < 8; t++) {
            int col = n0 + t * 8 + c2;
            float2 bv = *(const float2*)(bias + col);
            if (r < NODES) {
                *(__half2*)(C16 + (size_t)r * HD + col) =
                    __floats2half2_rn(fmaxf(acc[mi][t][0] + bv.x, 0.f),
                                      fmaxf(acc[mi][t][1] + bv.y, 0.f));
            }
            if (r + 8 < NODES) {
                *(__half2*)(C16 + (size_t)(r + 8) * HD + col) =
                    __floats2half2_rn(fmaxf(acc[mi][t][2] + bv.x, 0.f),
                                      fmaxf(acc[mi][t][3] + bv.y, 0.f));
            }
        }
    }
}

// ---------------- fused MLP: C16 = fp16(relu(relu(asum16@W1+b1)@W2 + b2 + h0_16)) --------------
__global__ __launch_bounds__(256, 2) void tgemm_fused_kernel(
    const __half* __restrict__ A16,
    const __half* __restrict__ W1f, const float* __restrict__ b1,
    const __half* __restrict__ W2f, const float* __restrict__ b2,
    const __half* __restrict__ res16, __half* __restrict__ C16) {
    extern __shared__ char sm[];
    uint32_t sb = smem_u32(sm);
    int tid = threadIdx.x;
    int lane = tid & 31, wid = tid >> 5;
    int bm = blockIdx.x * 128;

    stage_W(sb, W1f, tid);
    {
        const uint2* Hp = (const uint2*)A16;
#pragma unroll
        for (int i = 0; i < 16; i++) {
            int id4 = tid + i * 256;
            int m = id4 >> 5, k4 = id4 & 31;
            int gr = bm + m;
            if (gr >= NODES) gr = NODES - 1;
            float4 a = h4_to_f4(Hp[(size_t)gr * 32 + k4]);
            uint2 uh, ul;
            split_f16(a, uh, ul);
            int db = m * (PITCH * 2) + k4 * 8;
            *(uint2*)(sm + OFF_AH + db) = uh;
            *(uint2*)(sm + OFF_AL + db) = ul;
        }
    }
    asm volatile("cp.async.wait_group 0;" ::: "memory");
    __syncthreads();

    int mwarp = wid & 3, nwarp = wid >> 2;
    int m0 = mwarp * 32, n0 = nwarp * 64;
    uint32_t arow = (lane & 7) + ((lane >> 3) & 1) * 8;
    uint32_t acol = (lane >> 4) * 8;
    uint32_t aoff0 = ((m0 + arow) * PITCH + acol) * 2;
    uint32_t aoff1 = ((m0 + 16 + arow) * PITCH + acol) * 2;
    uint32_t boff = ((n0 + (lane & 7) + (lane >> 4) * 8) * PITCH + ((lane >> 3) & 1) * 8) * 2;

    float acc[2][8][4];
#pragma unroll
    for (int mi = 0; mi < 2; mi++)
#pragma unroll
        for (int t = 0; t < 8; t++)
#pragma unroll
            for (int j = 0; j < 4; j++) acc[mi][t][j] = 0.0f;

    // ---- GEMM1: t1 = relu(asum @ W1 + b1) ----
    mainloop(sb, aoff0, aoff1, boff, acc);

    __syncthreads();

    stage_W(sb, W2f, tid);   // async, overlaps t1 conversion

    int c2 = (lane & 3) * 2;
#pragma unroll
    for (int mi = 0; mi < 2; mi++) {
        int rl = m0 + mi * 16 + (lane >> 2);
#pragma unroll
        for (int t = 0; t < 8; t++) {
            int col = n0 + t * 8 + c2;
            float2 bv = *(const float2*)(b1 + col);
            float x0 = fmaxf(acc[mi][t][0] + bv.x, 0.f);
            float x1 = fmaxf(acc[mi][t][1] + bv.y, 0.f);
            float y0 = fmaxf(acc[mi][t][2] + bv.x, 0.f);
            float y1 = fmaxf(acc[mi][t][3] + bv.y, 0.f);
            uint32_t hi, lo;
            split_f16_pair(x0, x1, hi, lo);
            *(uint32_t*)(sm + OFF_AH + rl * (PITCH * 2) + col * 2) = hi;
            *(uint32_t*)(sm + OFF_AL + rl * (PITCH * 2) + col * 2) = lo;
            split_f16_pair(y0, y1, hi, lo);
            *(uint32_t*)(sm + OFF_AH + (rl + 8) * (PITCH * 2) + col * 2) = hi;
            *(uint32_t*)(sm + OFF_AL + (rl + 8) * (PITCH * 2) + col * 2) = lo;
        }
    }

#pragma unroll
    for (int mi = 0; mi < 2; mi++)
#pragma unroll
        for (int t = 0; t < 8; t++)
#pragma unroll
            for (int j = 0; j < 4; j++) acc[mi][t][j] = 0.0f;

    asm volatile("cp.async.wait_group 0;" ::: "memory");
    __syncthreads();

    // ---- GEMM2: h = relu(t1 @ W2 + b2 + h0) ----
    mainloop(sb, aoff0, aoff1, boff, acc);

#pragma unroll
    for (int mi = 0; mi < 2; mi++) {
        int r = bm + m0 + mi * 16 + (lane >> 2);
#pragma unroll
        for (int t = 0; t < 8; t++) {
            int col = n0 + t * 8 + c2;
            float2 bv = *(const float2*)(b2 + col);
            if (r < NODES) {
                float2 rv = __half22float2(*(const __half2*)(res16 + (size_t)r * HD + col));
                *(__half2*)(C16 + (size_t)r * HD + col) =
                    __floats2half2_rn(fmaxf(acc[mi][t][0] + bv.x + rv.x, 0.f),
                                      fmaxf(acc[mi][t][1] + bv.y + rv.y, 0.f));
            }
            if (r + 8 < NODES) {
                float2 rv = __half22float2(*(const __half2*)(res16 + (size_t)(r + 8) * HD + col));
                *(__half2*)(C16 + (size_t)(r + 8) * HD + col) =
                    __floats2half2_rn(fmaxf(acc[mi][t][2] + bv.x + rv.x, 0.f),
                                      fmaxf(acc[mi][t][3] + bv.y + rv.y, 0.f));
            }
        }
    }
}

// ---------------- pooling ----------------
__global__ void pool_kernel(const __half* __restrict__ h16, const int* __restrict__ batch,
                            float* __restrict__ pooled) {
    const int CH = 64;
    int t = threadIdx.x;
    int n0 = blockIdx.x * CH;
    int n1 = n0 + CH;
    if (n1 > NODES) n1 = NODES;
    float acc = 0.0f;
    int cur = batch[n0];
    for (int n = n0; n < n1; n++) {
        int g = batch[n];
        if (g != cur) {
            atomicAdd(&pooled[cur * HD + t], acc);
            acc = 0.0f;
            cur = g;
        }
        acc += __half2float(h16[(size_t)n * HD + t]);
    }
    atomicAdd(&pooled[cur * HD + t], acc);
}
__global__ void final_kernel(const float* __restrict__ pooled, const float* __restrict__ Wf,
                             const float* __restrict__ bf, float* __restrict__ out) {
    int g = blockIdx.x, t = threadIdx.x;
    __shared__ float sm[128];
    sm[t] = pooled[g * HD + t] * Wf[t];
    __syncthreads();
#pragma unroll
    for (int o = 64; o > 0; o >>= 1) {
        if (t < o) sm[t] += sm[t + o];
        __syncthreads();
    }
    if (t == 0) out[g] = sm[0] + bf[0];
}

// ---------------- launch ----------------
extern "C" void kernel_launch(void* const* d_in, const int* in_sizes, int n_in,
                              void* d_out, int out_size) {
    const float* x  = (const float*)d_in[0];
    const int* ei   = (const int*)d_in[1];
    const int* batch = (const int*)d_in[3];
    const float* W0 = (const float*)d_in[4];
    const float* b0 = (const float*)d_in[5];
    const float* W1 = (const float*)d_in[6];
    const float* b1 = (const float*)d_in[7];
    const float* W2 = (const float*)d_in[8];
    const float* b2 = (const float*)d_in[9];
    const float* Wf = (const float*)d_in[10];
    const float* bf = (const float*)d_in[11];
    float* out = (float*)d_out;
    int E = in_sizes[1] / 2;

    cudaFuncSetAttribute(tgemm_kernel, cudaFuncAttributeMaxDynamicSharedMemorySize, SM_TOT);
    cudaFuncSetAttribute(tgemm_fused_kernel, cudaFuncAttributeMaxDynamicSharedMemorySize, SM_TOT);

    float *pooled;
    __half *h0x, *hx, *asum, *wfmt;
    int *rowptr, *cursor, *csr, *bsums;
    cudaGetSymbolAddress((void**)&h0x, g_h0x);
    cudaGetSymbolAddress((void**)&hx, g_hx);
    cudaGetSymbolAddress((void**)&asum, g_asum);
    cudaGetSymbolAddress((void**)&pooled, g_pooled);
    cudaGetSymbolAddress((void**)&rowptr, g_rowptr);
    cudaGetSymbolAddress((void**)&cursor, g_cursor);
    cudaGetSymbolAddress((void**)&csr, g_csr);
    cudaGetSymbolAddress((void**)&bsums, g_bsums);
    cudaGetSymbolAddress((void**)&wfmt, g_wfmt);

    int nb = (NODES + 255) / 256;

    wfmt_kernel<<<dim3(9, 16), 256>>>(W0, W1, W2, wfmt);

    zero_int_kernel<<<(NODES + 1 + 255) / 256, 256>>>(rowptr, NODES + 1);
    hist_kernel<<<(E + 255) / 256, 256>>>(ei, rowptr, E);
    scan_blocks_kernel<<<nb, 256>>>(rowptr, bsums, NODES);
    scan_bsums_kernel<<<1, 512>>>(bsums, nb);
    scan_finish_kernel<<<nb, 256>>>(rowptr, bsums, cursor, NODES, E);
    fill_csr_kernel<<<(E + 255) / 256, 256>>>(ei, cursor, csr, E);

    int gg = (NODES + 127) / 128;  // 782

    // h0 = fp16(relu(x @ W0 + b0))
    tgemm_kernel<<<gg, 256, SM_TOT>>>(x, wfmt, b0, h0x);

    for (int i = 0; i < 4; i++) {
        const __half* hcur = (i == 0) ? h0x : hx;
        agg_kernel<<<(NODES * 32 + 255) / 256, 256>>>(rowptr, csr, hcur, asum);
        tgemm_fused_kernel<<<gg, 256, SM_TOT>>>(asum,
                                                wfmt + (size_t)(1 + i) * 16384, b1 + i * HD,
                                                wfmt + (size_t)(5 + i) * 16384, b2 + i * HD,
                                                h0x, hx);
    }

    zero_float_kernel<<<(NGR * HD + 255) / 256, 256>>>(pooled, NGR * HD);
    pool_kernel<<<(NODES + 63) / 64, 128>>>(hx, batch, pooled);
    final_kernel<<<NGR, 128>>>(pooled, Wf, bf, out);
}

// round 14
// speedup vs baseline: 1.0043x; 1.0043x over previous
#include <cuda_runtime.h>
#include <cuda_fp16.h>
#include <cstdint>

#define NODES 100000
#define NGR   1000
#define HD    128
#define NEDGE 1600000

// ---------------- scratch (activations fp16; fp32 accumulate) ----------------
__device__ __half g_h0x[NODES * HD];    // h0 fp16
__device__ __half g_hx[NODES * HD];     // current h fp16
__device__ __half g_asum[NODES * HD];   // self + neighbor sum, fp16
__device__ float g_pooled[NGR * HD];
__device__ int   g_rowptr[NODES + 1];
__device__ int   g_cursor[NODES];
__device__ int   g_csr[NEDGE];
__device__ int   g_bsums[512];
__device__ __half g_wfmt[9 * 16384];    // 9 mats x Wt[n][k] fp16

// ---------------- ptx helpers ----------------
__device__ __forceinline__ uint32_t smem_u32(const void* p) {
    uint32_t a;
    asm("{ .reg .u64 t; cvta.to.shared.u64 t, %1; cvt.u32.u64 %0, t; }" : "=r"(a) : "l"(p));
    return a;
}
__device__ __forceinline__ void ldsm4(uint32_t* r, uint32_t a) {
    asm volatile("ldmatrix.sync.aligned.m8n8.x4.shared.b16 {%0,%1,%2,%3}, [%4];"
                 : "=r"(r[0]), "=r"(r[1]), "=r"(r[2]), "=r"(r[3]) : "r"(a));
}
__device__ __forceinline__ void cpasync16(uint32_t dst, const void* src) {
    asm volatile("cp.async.cg.shared.global [%0], [%1], 16;" :: "r"(dst), "l"(src));
}
#define MMA_F16(ac, af, b0, b1)                                                     \
    asm volatile(                                                                   \
        "mma.sync.aligned.m16n8k16.row.col.f32.f16.f16.f32 "                        \
        "{%0,%1,%2,%3}, {%4,%5,%6,%7}, {%8,%9}, {%0,%1,%2,%3};"                     \
        : "+f"((ac)[0]), "+f"((ac)[1]), "+f"((ac)[2]), "+f"((ac)[3])                \
        : "r"((af)[0]), "r"((af)[1]), "r"((af)[2]), "r"((af)[3]), "r"(b0), "r"(b1))

__device__ __forceinline__ void split_f16(float4 g, uint2& uh, uint2& ul) {
    __half2 h01 = __floats2half2_rn(g.x, g.y);
    __half2 h23 = __floats2half2_rn(g.z, g.w);
    float lx = g.x - __half2float(__low2half(h01));
    float ly = g.y - __half2float(__high2half(h01));
    float lz = g.z - __half2float(__low2half(h23));
    float lw = g.w - __half2float(__high2half(h23));
    __half2 l01 = __floats2half2_rn(lx, ly);
    __half2 l23 = __floats2half2_rn(lz, lw);
    uh.x = *(uint32_t*)&h01; uh.y = *(uint32_t*)&h23;
    ul.x = *(uint32_t*)&l01; ul.y = *(uint32_t*)&l23;
}
__device__ __forceinline__ void split_f16_pair(float a, float b, uint32_t& hi, uint32_t& lo) {
    __half2 h = __floats2half2_rn(a, b);
    float la = a - __half2float(__low2half(h));
    float lb = b - __half2float(__high2half(h));
    __half2 l = __floats2half2_rn(la, lb);
    hi = *(uint32_t*)&h;
    lo = *(uint32_t*)&l;
}
__device__ __forceinline__ float4 h4_to_f4(uint2 v) {
    float2 fa = __half22float2(*(__half2*)&v.x);
    float2 fb = __half22float2(*(__half2*)&v.y);
    return make_float4(fa.x, fa.y, fb.x, fb.y);
}

// ---------------- weight pre-format ----------------
__global__ void wfmt_kernel(const float* __restrict__ W0, const float* __restrict__ W1,
                            const float* __restrict__ W2, __half* __restrict__ out) {
    int mat = blockIdx.x;
    int chunk = blockIdx.y;
    const float* W = (mat == 0) ? W0 : (mat <= 4 ? W1 + (mat - 1) * HD * HD
                                                 : W2 + (mat - 5) * HD * HD);
    __half* o = out + (size_t)mat * 16384;
    int base = chunk * 1024;
    for (int i = threadIdx.x; i < 1024; i += blockDim.x) {
        int id = base + i;
        int k = id >> 7, n = id & 127;
        o[n * HD + k] = __float2half(W[id]);
    }
}

// ---------------- utility ----------------
__global__ void zero_int_kernel(int* p, int n) {
    int i = blockIdx.x * blockDim.x + threadIdx.x;
    if (i < n) p[i] = 0;
}
__global__ void zero_float_kernel(float* p, int n) {
    int i = blockIdx.x * blockDim.x + threadIdx.x;
    if (i < n) p[i] = 0.0f;
}

// ---------------- CSR build ----------------
__global__ void hist_kernel(const int* __restrict__ ei, int* __restrict__ deg, int E) {
    int e = blockIdx.x * blockDim.x + threadIdx.x;
    if (e < E) atomicAdd(&deg[ei[E + e]], 1);
}
__global__ void scan_blocks_kernel(int* __restrict__ data, int* __restrict__ bsums, int n) {
    int tid = threadIdx.x;
    int i = blockIdx.x * 256 + tid;
    int v = (i < n) ? data[i] : 0;
    int x = v;
#pragma unroll
    for (int o = 1; o < 32; o <<= 1) {
        int y = __shfl_up_sync(0xffffffffu, x, o);
        if ((tid & 31) >= o) x += y;
    }
    __shared__ int ws[8];
    if ((tid & 31) == 31) ws[tid >> 5] = x;
    __syncthreads();
    if (tid == 0) {
        int run = 0;
#pragma unroll
        for (int w = 0; w < 8; w++) { int t = ws[w]; ws[w] = run; run += t; }
    }
    __syncthreads();
    int incl = x + ws[tid >> 5];
    if (i < n) data[i] = incl - v;
    if (tid == 255) bsums[blockIdx.x] = incl;
}
__global__ void scan_bsums_kernel(int* bsums, int nb) {
    int tid = threadIdx.x;
    int v = (tid < nb) ? bsums[tid] : 0;
    int x = v;
#pragma unroll
    for (int o = 1; o < 32; o <<= 1) {
        int y = __shfl_up_sync(0xffffffffu, x, o);
        if ((tid & 31) >= o) x += y;
    }
    __shared__ int ws[16];
    if ((tid & 31) == 31) ws[tid >> 5] = x;
    __syncthreads();
    if (tid == 0) {
        int run = 0;
#pragma unroll
        for (int w = 0; w < 16; w++) { int t = ws[w]; ws[w] = run; run += t; }
    }
    __syncthreads();
    int incl = x + ws[tid >> 5];
    if (tid < nb) bsums[tid] = incl - v;
}
__global__ void scan_finish_kernel(int* __restrict__ rowptr, const int* __restrict__ bsums,
                                   int* __restrict__ cursor, int n, int E) {
    int i = blockIdx.x * 256 + threadIdx.x;
    if (i < n) {
        int v = rowptr[i] + bsums[blockIdx.x];
        rowptr[i] = v;
        cursor[i] = v;
    }
    if (i == 0) rowptr[n] = E;
}
__global__ void fill_csr_kernel(const int* __restrict__ ei, int* __restrict__ cursor,
                                int* __restrict__ csr, int E) {
    int e = blockIdx.x * blockDim.x + threadIdx.x;
    if (e < E) {
        int s = ei[e];
        int d = ei[E + e];
        int p = atomicAdd(&cursor[d], 1);
        csr[p] = s;
    }
}

// ---------------- aggregation: asum = h[node] + sum_j h[j]  (fp32 acc, fp16 out) --------------
__global__ void agg_kernel(const int* __restrict__ rp, const int* __restrict__ cs,
                           const __half* __restrict__ h16, __half* __restrict__ asum16) {
    int gw = (blockIdx.x * blockDim.x + threadIdx.x) >> 5;
    int lane = threadIdx.x & 31;
    if (gw >= NODES) return;
    int s = rp[gw], e = rp[gw + 1];
    const uint2* h2 = (const uint2*)h16;
    float4 acc = h4_to_f4(__ldg(&h2[(size_t)gw * 32 + lane]));   // self term
    int i = s;
    for (; i + 3 < e; i += 4) {
        int u0 = cs[i], u1 = cs[i + 1], u2 = cs[i + 2], u3 = cs[i + 3];
        float4 v0 = h4_to_f4(__ldg(&h2[(size_t)u0 * 32 + lane]));
        float4 v1 = h4_to_f4(__ldg(&h2[(size_t)u1 * 32 + lane]));
        float4 v2 = h4_to_f4(__ldg(&h2[(size_t)u2 * 32 + lane]));
        float4 v3 = h4_to_f4(__ldg(&h2[(size_t)u3 * 32 + lane]));
        acc.x += (v0.x + v1.x) + (v2.x + v3.x);
        acc.y += (v0.y + v1.y) + (v2.y + v3.y);
        acc.z += (v0.z + v1.z) + (v2.z + v3.z);
        acc.w += (v0.w + v1.w) + (v2.w + v3.w);
    }
    for (; i < e; i++) {
        int u = cs[i];
        float4 v = h4_to_f4(__ldg(&h2[(size_t)u * 32 + lane]));
        acc.x += v.x; acc.y += v.y; acc.z += v.z; acc.w += v.w;
    }
    __half2 p01 = __floats2half2_rn(acc.x, acc.y);
    __half2 p23 = __floats2half2_rn(acc.z, acc.w);
    uint2 o;
    o.x = *(uint32_t*)&p01;
    o.y = *(uint32_t*)&p23;
    ((uint2*)asum16)[(size_t)gw * 32 + lane] = o;
}

// ---------------- GEMM tile machinery: 128 rows/CTA, 256 threads (4M x 2N warps) --------------
#define PITCH 136
#define OFF_AH 0
#define OFF_AL (128 * PITCH * 2)            // 34816
#define OFF_B  (2 * 128 * PITCH * 2)        // 69632
#define SM_TOT (OFF_B + 128 * PITCH * 2)    // 104448 -> 2 CTAs/SM

__device__ __forceinline__ void stage_W(uint32_t sb, const __half* Wfmt, int tid) {
    const float4* src = (const float4*)Wfmt;
#pragma unroll
    for (int i = 0; i < 8; i++) {
        int id = tid + i * 256;             // 2048 float4
        int n = id >> 4, c = id & 15;
        cpasync16(sb + OFF_B + n * (PITCH * 2) + c * 16, src + id);
    }
    asm volatile("cp.async.commit_group;" ::: "memory");
}

__device__ __forceinline__ void mainloop(uint32_t sb, uint32_t aoff0, uint32_t aoff1,
                                         uint32_t boff, float acc[2][8][4]) {
#pragma unroll
    for (int ks = 0; ks < 8; ks++) {
        uint32_t kb = ks * 32;
        uint32_t ah[2][4], al[2][4], b[4][4];
        ldsm4(ah[0], sb + OFF_AH + aoff0 + kb);
        ldsm4(ah[1], sb + OFF_AH + aoff1 + kb);
        ldsm4(al[0], sb + OFF_AL + aoff0 + kb);
        ldsm4(al[1], sb + OFF_AL + aoff1 + kb);
#pragma unroll
        for (int nt = 0; nt < 4; nt++)
            ldsm4(b[nt], sb + OFF_B + boff + nt * 16 * (PITCH * 2) + kb);
#pragma unroll
        for (int mi = 0; mi < 2; mi++)
#pragma unroll
            for (int nt = 0; nt < 4; nt++) {
                MMA_F16(acc[mi][2 * nt],     ah[mi], b[nt][0], b[nt][1]);
                MMA_F16(acc[mi][2 * nt],     al[mi], b[nt][0], b[nt][1]);
                MMA_F16(acc[mi][2 * nt + 1], ah[mi], b[nt][2], b[nt][3]);
                MMA_F16(acc[mi][2 * nt + 1], al[mi], b[nt][2], b[nt][3]);
            }
    }
}

// ---------------- GEMM0: C16 = fp16(relu(x @ W + b)), x fp32 ----------------
__global__ __launch_bounds__(256, 2) void tgemm_kernel(
    const float* __restrict__ A, const __half* __restrict__ Wfmt,
    const float* __restrict__ bias, __half* __restrict__ C16) {
    extern __shared__ char sm[];
    uint32_t sb = smem_u32(sm);
    int tid = threadIdx.x;
    int lane = tid & 31, wid = tid >> 5;
    int bm = blockIdx.x * 128;

    stage_W(sb, Wfmt, tid);
    {
        const float4* Ap = (const float4*)A;
#pragma unroll
        for (int i = 0; i < 16; i++) {
            int id4 = tid + i * 256;        // 4096 float4 = 128 rows x 32
            int m = id4 >> 5, k4 = id4 & 31;
            int gr = bm + m;
            if (gr >= NODES) gr = NODES - 1;
            float4 g = Ap[(size_t)gr * 32 + k4];
            uint2 uh, ul;
            split_f16(g, uh, ul);
            int db = m * (PITCH * 2) + k4 * 8;
            *(uint2*)(sm + OFF_AH + db) = uh;
            *(uint2*)(sm + OFF_AL + db) = ul;
        }
    }
    asm volatile("cp.async.wait_group 0;" ::: "memory");
    __syncthreads();

    int mwarp = wid & 3, nwarp = wid >> 2;
    int m0 = mwarp * 32, n0 = nwarp * 64;
    uint32_t arow = (lane & 7) + ((lane >> 3) & 1) * 8;
    uint32_t acol = (lane >> 4) * 8;
    uint32_t aoff0 = ((m0 + arow) * PITCH + acol) * 2;
    uint32_t aoff1 = ((m0 + 16 + arow) * PITCH + acol) * 2;
    uint32_t boff = ((n0 + (lane & 7) + (lane >> 4) * 8) * PITCH + ((lane >> 3) & 1) * 8) * 2;

    float acc[2][8][4];
#pragma unroll
    for (int mi = 0; mi < 2; mi++)
#pragma unroll
        for (int t = 0; t < 8; t++)
#pragma unroll
            for (int j = 0; j < 4; j++) acc[mi][t][j] = 0.0f;

    mainloop(sb, aoff0, aoff1, boff, acc);

    int c2 = (lane & 3) * 2;
#pragma unroll
    for (int mi = 0; mi < 2; mi++) {
        int r = bm + m0 + mi * 16 + (lane >> 2);
#pragma unroll
        for (int t = 0; t < 8; t++) {
            int col = n0 + t * 8 + c2;
            float2 bv = *(const float2*)(bias + col);
            if (r < NODES) {
                *(__half2*)(C16 + (size_t)r * HD + col) =
                    __floats2half2_rn(fmaxf(acc[mi][t][0] + bv.x, 0.f),
                                      fmaxf(acc[mi][t][1] + bv.y, 0.f));
            }
            if (r + 8 < NODES) {
                *(__half2*)(C16 + (size_t)(r + 8) * HD + col) =
                    __floats2half2_rn(fmaxf(acc[mi][t][2] + bv.x, 0.f),
                                      fmaxf(acc[mi][t][3] + bv.y, 0.f));
            }
        }
    }
}

// ---------------- fused MLP: C16 = fp16(relu(relu(asum16@W1+b1)@W2 + b2 + h0_16)) --------------
__global__ __launch_bounds__(256, 2) void tgemm_fused_kernel(
    const __half* __restrict__ A16,
    const __half* __restrict__ W1f, const float* __restrict__ b1,
    const __half* __restrict__ W2f, const float* __restrict__ b2,
    const __half* __restrict__ res16, __half* __restrict__ C16) {
    extern __shared__ char sm[];
    uint32_t sb = smem_u32(sm);
    int tid = threadIdx.x;
    int lane = tid & 31, wid = tid >> 5;
    int bm = blockIdx.x * 128;

    stage_W(sb, W1f, tid);
    {
        const uint2* Hp = (const uint2*)A16;
#pragma unroll
        for (int i = 0; i < 16; i++) {
            int id4 = tid + i * 256;
            int m = id4 >> 5, k4 = id4 & 31;
            int gr = bm + m;
            if (gr >= NODES) gr = NODES - 1;
            float4 a = h4_to_f4(Hp[(size_t)gr * 32 + k4]);
            uint2 uh, ul;
            split_f16(a, uh, ul);
            int db = m * (PITCH * 2) + k4 * 8;
            *(uint2*)(sm + OFF_AH + db) = uh;
            *(uint2*)(sm + OFF_AL + db) = ul;
        }
    }
    asm volatile("cp.async.wait_group 0;" ::: "memory");
    __syncthreads();

    int mwarp = wid & 3, nwarp = wid >> 2;
    int m0 = mwarp * 32, n0 = nwarp * 64;
    uint32_t arow = (lane & 7) + ((lane >> 3) & 1) * 8;
    uint32_t acol = (lane >> 4) * 8;
    uint32_t aoff0 = ((m0 + arow) * PITCH + acol) * 2;
    uint32_t aoff1 = ((m0 + 16 + arow) * PITCH + acol) * 2;
    uint32_t boff = ((n0 + (lane & 7) + (lane >> 4) * 8) * PITCH + ((lane >> 3) & 1) * 8) * 2;

    float acc[2][8][4];
#pragma unroll
    for (int mi = 0; mi < 2; mi++)
#pragma unroll
        for (int t = 0; t < 8; t++)
#pragma unroll
            for (int j = 0; j < 4; j++) acc[mi][t][j] = 0.0f;

    // ---- GEMM1: t1 = relu(asum @ W1 + b1) ----
    mainloop(sb, aoff0, aoff1, boff, acc);

    __syncthreads();

    stage_W(sb, W2f, tid);   // async, overlaps t1 conversion

    int c2 = (lane & 3) * 2;
#pragma unroll
    for (int mi = 0; mi < 2; mi++) {
        int rl = m0 + mi * 16 + (lane >> 2);
#pragma unroll
        for (int t = 0; t < 8; t++) {
            int col = n0 + t * 8 + c2;
            float2 bv = *(const float2*)(b1 + col);
            float x0 = fmaxf(acc[mi][t][0] + bv.x, 0.f);
            float x1 = fmaxf(acc[mi][t][1] + bv.y, 0.f);
            float y0 = fmaxf(acc[mi][t][2] + bv.x, 0.f);
            float y1 = fmaxf(acc[mi][t][3] + bv.y, 0.f);
            uint32_t hi, lo;
            split_f16_pair(x0, x1, hi, lo);
            *(uint32_t*)(sm + OFF_AH + rl * (PITCH * 2) + col * 2) = hi;
            *(uint32_t*)(sm + OFF_AL + rl * (PITCH * 2) + col * 2) = lo;
            split_f16_pair(y0, y1, hi, lo);
            *(uint32_t*)(sm + OFF_AH + (rl + 8) * (PITCH * 2) + col * 2) = hi;
            *(uint32_t*)(sm + OFF_AL + (rl + 8) * (PITCH * 2) + col * 2) = lo;
        }
    }

#pragma unroll
    for (int mi = 0; mi < 2; mi++)
#pragma unroll
        for (int t = 0; t < 8; t++)
#pragma unroll
            for (int j = 0; j < 4; j++) acc[mi][t][j] = 0.0f;

    asm volatile("cp.async.wait_group 0;" ::: "memory");
    __syncthreads();

    // ---- GEMM2: h = relu(t1 @ W2 + b2 + h0) ----
    mainloop(sb, aoff0, aoff1, boff, acc);

#pragma unroll
    for (int mi = 0; mi < 2; mi++) {
        int r = bm + m0 + mi * 16 + (lane >> 2);
#pragma unroll
        for (int t = 0; t < 8; t++) {
            int col = n0 + t * 8 + c2;
            float2 bv = *(const float2*)(b2 + col);
            if (r < NODES) {
                float2 rv = __half22float2(*(const __half2*)(res16 + (size_t)r * HD + col));
                *(__half2*)(C16 + (size_t)r * HD + col) =
                    __floats2half2_rn(fmaxf(acc[mi][t][0] + bv.x + rv.x, 0.f),
                                      fmaxf(acc[mi][t][1] + bv.y + rv.y, 0.f));
            }
            if (r + 8 < NODES) {
                float2 rv = __half22float2(*(const __half2*)(res16 + (size_t)(r + 8) * HD + col));
                *(__half2*)(C16 + (size_t)(r + 8) * HD + col) =
                    __floats2half2_rn(fmaxf(acc[mi][t][2] + bv.x + rv.x, 0.f),
                                      fmaxf(acc[mi][t][3] + bv.y + rv.y, 0.f));
            }
        }
    }
}

// ---------------- pooling ----------------
__global__ void pool_kernel(const __half* __restrict__ h16, const int* __restrict__ batch,
                            float* __restrict__ pooled) {
    const int CH = 64;
    int t = threadIdx.x;
    int n0 = blockIdx.x * CH;
    int n1 = n0 + CH;
    if (n1 > NODES) n1 = NODES;
    float acc = 0.0f;
    int cur = batch[n0];
    for (int n = n0; n < n1; n++) {
        int g = batch[n];
        if (g != cur) {
            atomicAdd(&pooled[cur * HD + t], acc);
            acc = 0.0f;
            cur = g;
        }
        acc += __half2float(h16[(size_t)n * HD + t]);
    }
    atomicAdd(&pooled[cur * HD + t], acc);
}
__global__ void final_kernel(const float* __restrict__ pooled, const float* __restrict__ Wf,
                             const float* __restrict__ bf, float* __restrict__ out) {
    int g = blockIdx.x, t = threadIdx.x;
    __shared__ float sm[128];
    sm[t] = pooled[g * HD + t] * Wf[t];
    __syncthreads();
#pragma unroll
    for (int o = 64; o > 0; o >>= 1) {
        if (t < o) sm[t] += sm[t + o];
        __syncthreads();
    }
    if (t == 0) out[g] = sm[0] + bf[0];
}

// ---------------- launch ----------------
extern "C" void kernel_launch(void* const* d_in, const int* in_sizes, int n_in,
                              void* d_out, int out_size) {
    const float* x  = (const float*)d_in[0];
    const int* ei   = (const int*)d_in[1];
    const int* batch = (const int*)d_in[3];
    const float* W0 = (const float*)d_in[4];
    const float* b0 = (const float*)d_in[5];
    const float* W1 = (const float*)d_in[6];
    const float* b1 = (const float*)d_in[7];
    const float* W2 = (const float*)d_in[8];
    const float* b2 = (const float*)d_in[9];
    const float* Wf = (const float*)d_in[10];
    const float* bf = (const float*)d_in[11];
    float* out = (float*)d_out;
    int E = in_sizes[1] / 2;

    cudaFuncSetAttribute(tgemm_kernel, cudaFuncAttributeMaxDynamicSharedMemorySize, SM_TOT);
    cudaFuncSetAttribute(tgemm_fused_kernel, cudaFuncAttributeMaxDynamicSharedMemorySize, SM_TOT);

    float *pooled;
    __half *h0x, *hx, *asum, *wfmt;
    int *rowptr, *cursor, *csr, *bsums;
    cudaGetSymbolAddress((void**)&h0x, g_h0x);
    cudaGetSymbolAddress((void**)&hx, g_hx);
    cudaGetSymbolAddress((void**)&asum, g_asum);
    cudaGetSymbolAddress((void**)&pooled, g_pooled);
    cudaGetSymbolAddress((void**)&rowptr, g_rowptr);
    cudaGetSymbolAddress((void**)&cursor, g_cursor);
    cudaGetSymbolAddress((void**)&csr, g_csr);
    cudaGetSymbolAddress((void**)&bsums, g_bsums);
    cudaGetSymbolAddress((void**)&wfmt, g_wfmt);

    int nb = (NODES + 255) / 256;

    wfmt_kernel<<<dim3(9, 16), 256>>>(W0, W1, W2, wfmt);

    zero_int_kernel<<<(NODES + 1 + 255) / 256, 256>>>(rowptr, NODES + 1);
    hist_kernel<<<(E + 255) / 256, 256>>>(ei, rowptr, E);
    scan_blocks_kernel<<<nb, 256>>>(rowptr, bsums, NODES);
    scan_bsums_kernel<<<1, 512>>>(bsums, nb);
    scan_finish_kernel<<<nb, 256>>>(rowptr, bsums, cursor, NODES, E);
    fill_csr_kernel<<<(E + 255) / 256, 256>>>(ei, cursor, csr, E);

    int gg = (NODES + 127) / 128;  // 782

    // h0 = fp16(relu(x @ W0 + b0))
    tgemm_kernel<<<gg, 256, SM_TOT>>>(x, wfmt, b0, h0x);

    for (int i = 0; i < 4; i++) {
        const __half* hcur = (i == 0) ? h0x : hx;
        agg_kernel<<<(NODES * 32 + 255) / 256, 256>>>(rowptr, csr, hcur, asum);
        tgemm_fused_kernel<<<gg, 256, SM_TOT>>>(asum,
                                                wfmt + (size_t)(1 + i) * 16384, b1 + i * HD,
                                                wfmt + (size_t)(5 + i) * 16384, b2 + i * HD,
                                                h0x, hx);
    }

    zero_float_kernel<<<(NGR * HD + 255) / 256, 256>>>(pooled, NGR * HD);
    pool_kernel<<<(NODES + 63) / 64, 128>>>(hx, batch, pooled);
    final_kernel<<<NGR, 128>>>(pooled, Wf, bf, out);
}

// round 15
// speedup vs baseline: 1.0351x; 1.0307x over previous
#include <cuda_runtime.h>
#include <cuda_fp16.h>
#include <cstdint>

#define NODES 100000
#define NGR   1000
#define HD    128
#define NEDGE 1600000

// ---------------- scratch (activations fp16; fp32 accumulate) ----------------
__device__ __half g_h0x[NODES * HD];    // h0 fp16
__device__ __half g_hx[NODES * HD];     // current h fp16
__device__ __half g_asum[NODES * HD];   // self + neighbor sum, fp16
__device__ float g_pooled[NGR * HD];
__device__ int   g_rowptr[NODES + 1];
__device__ int   g_cursor[NODES];
__device__ int   g_csr[NEDGE];
__device__ int   g_bsums[512];
__device__ __half g_wfmt[9 * 16384];    // 9 mats x Wt[n][k] fp16

// ---------------- ptx helpers ----------------
__device__ __forceinline__ uint32_t smem_u32(const void* p) {
    uint32_t a;
    asm("{ .reg .u64 t; cvta.to.shared.u64 t, %1; cvt.u32.u64 %0, t; }" : "=r"(a) : "l"(p));
    return a;
}
__device__ __forceinline__ void ldsm4(uint32_t* r, uint32_t a) {
    asm volatile("ldmatrix.sync.aligned.m8n8.x4.shared.b16 {%0,%1,%2,%3}, [%4];"
                 : "=r"(r[0]), "=r"(r[1]), "=r"(r[2]), "=r"(r[3]) : "r"(a));
}
__device__ __forceinline__ void cpasync16(uint32_t dst, const void* src) {
    asm volatile("cp.async.cg.shared.global [%0], [%1], 16;" :: "r"(dst), "l"(src));
}
#define MMA_F16(ac, af, b0, b1)                                                     \
    asm volatile(                                                                   \
        "mma.sync.aligned.m16n8k16.row.col.f32.f16.f16.f32 "                        \
        "{%0,%1,%2,%3}, {%4,%5,%6,%7}, {%8,%9}, {%0,%1,%2,%3};"                     \
        : "+f"((ac)[0]), "+f"((ac)[1]), "+f"((ac)[2]), "+f"((ac)[3])                \
        : "r"((af)[0]), "r"((af)[1]), "r"((af)[2]), "r"((af)[3]), "r"(b0), "r"(b1))

__device__ __forceinline__ void split_f16(float4 g, uint2& uh, uint2& ul) {
    __half2 h01 = __floats2half2_rn(g.x, g.y);
    __half2 h23 = __floats2half2_rn(g.z, g.w);
    float lx = g.x - __half2float(__low2half(h01));
    float ly = g.y - __half2float(__high2half(h01));
    float lz = g.z - __half2float(__low2half(h23));
    float lw = g.w - __half2float(__high2half(h23));
    __half2 l01 = __floats2half2_rn(lx, ly);
    __half2 l23 = __floats2half2_rn(lz, lw);
    uh.x = *(uint32_t*)&h01; uh.y = *(uint32_t*)&h23;
    ul.x = *(uint32_t*)&l01; ul.y = *(uint32_t*)&l23;
}
__device__ __forceinline__ void split_f16_pair(float a, float b, uint32_t& hi, uint32_t& lo) {
    __half2 h = __floats2half2_rn(a, b);
    float la = a - __half2float(__low2half(h));
    float lb = b - __half2float(__high2half(h));
    __half2 l = __floats2half2_rn(la, lb);
    hi = *(uint32_t*)&h;
    lo = *(uint32_t*)&l;
}
__device__ __forceinline__ float4 h4_to_f4(uint2 v) {
    float2 fa = __half22float2(*(__half2*)&v.x);
    float2 fb = __half22float2(*(__half2*)&v.y);
    return make_float4(fa.x, fa.y, fb.x, fb.y);
}

// ---------------- weight pre-format ----------------
__global__ void wfmt_kernel(const float* __restrict__ W0, const float* __restrict__ W1,
                            const float* __restrict__ W2, __half* __restrict__ out) {
    int mat = blockIdx.x;
    int chunk = blockIdx.y;
    const float* W = (mat == 0) ? W0 : (mat <= 4 ? W1 + (mat - 1) * HD * HD
                                                 : W2 + (mat - 5) * HD * HD);
    __half* o = out + (size_t)mat * 16384;
    int base = chunk * 1024;
    for (int i = threadIdx.x; i < 1024; i += blockDim.x) {
        int id = base + i;
        int k = id >> 7, n = id & 127;
        o[n * HD + k] = __float2half(W[id]);
    }
}

// ---------------- utility ----------------
__global__ void zero_int_kernel(int* p, int n) {
    int i = blockIdx.x * blockDim.x + threadIdx.x;
    if (i < n) p[i] = 0;
}
__global__ void zero_float_kernel(float* p, int n) {
    int i = blockIdx.x * blockDim.x + threadIdx.x;
    if (i < n) p[i] = 0.0f;
}

// ---------------- CSR build ----------------
__global__ void hist_kernel(const int* __restrict__ ei, int* __restrict__ deg, int E) {
    int e = blockIdx.x * blockDim.x + threadIdx.x;
    if (e < E) atomicAdd(&deg[ei[E + e]], 1);
}
__global__ void scan_blocks_kernel(int* __restrict__ data, int* __restrict__ bsums, int n) {
    int tid = threadIdx.x;
    int i = blockIdx.x * 256 + tid;
    int v = (i < n) ? data[i] : 0;
    int x = v;
#pragma unroll
    for (int o = 1; o < 32; o <<= 1) {
        int y = __shfl_up_sync(0xffffffffu, x, o);
        if ((tid & 31) >= o) x += y;
    }
    __shared__ int ws[8];
    if ((tid & 31) == 31) ws[tid >> 5] = x;
    __syncthreads();
    if (tid == 0) {
        int run = 0;
#pragma unroll
        for (int w = 0; w < 8; w++) { int t = ws[w]; ws[w] = run; run += t; }
    }
    __syncthreads();
    int incl = x + ws[tid >> 5];
    if (i < n) data[i] = incl - v;
    if (tid == 255) bsums[blockIdx.x] = incl;
}
__global__ void scan_bsums_kernel(int* bsums, int nb) {
    int tid = threadIdx.x;
    int v = (tid < nb) ? bsums[tid] : 0;
    int x = v;
#pragma unroll
    for (int o = 1; o < 32; o <<= 1) {
        int y = __shfl_up_sync(0xffffffffu, x, o);
        if ((tid & 31) >= o) x += y;
    }
    __shared__ int ws[16];
    if ((tid & 31) == 31) ws[tid >> 5] = x;
    __syncthreads();
    if (tid == 0) {
        int run = 0;
#pragma unroll
        for (int w = 0; w < 16; w++) { int t = ws[w]; ws[w] = run; run += t; }
    }
    __syncthreads();
    int incl = x + ws[tid >> 5];
    if (tid < nb) bsums[tid] = incl - v;
}
__global__ void scan_finish_kernel(int* __restrict__ rowptr, const int* __restrict__ bsums,
                                   int* __restrict__ cursor, int n, int E) {
    int i = blockIdx.x * 256 + threadIdx.x;
    if (i < n) {
        int v = rowptr[i] + bsums[blockIdx.x];
        rowptr[i] = v;
        cursor[i] = v;
    }
    if (i == 0) rowptr[n] = E;
}
__global__ void fill_csr_kernel(const int* __restrict__ ei, int* __restrict__ cursor,
                                int* __restrict__ csr, int E) {
    int e = blockIdx.x * blockDim.x + threadIdx.x;
    if (e < E) {
        int s = ei[e];
        int d = ei[E + e];
        int p = atomicAdd(&cursor[d], 1);
        csr[p] = s;
    }
}

// ---------------- aggregation: asum = h[node] + sum_j h[j]  (fp32 acc, fp16 out) --------------
__global__ void agg_kernel(const int* __restrict__ rp, const int* __restrict__ cs,
                           const __half* __restrict__ h16, __half* __restrict__ asum16) {
    int gw = (blockIdx.x * blockDim.x + threadIdx.x) >> 5;
    int lane = threadIdx.x & 31;
    if (gw >= NODES) return;
    int s = rp[gw], e = rp[gw + 1];
    const uint2* h2 = (const uint2*)h16;
    float4 acc = h4_to_f4(__ldg(&h2[(size_t)gw * 32 + lane]));   // self term
    int i = s;
    for (; i + 3 < e; i += 4) {
        int u0 = cs[i], u1 = cs[i + 1], u2 = cs[i + 2], u3 = cs[i + 3];
        float4 v0 = h4_to_f4(__ldg(&h2[(size_t)u0 * 32 + lane]));
        float4 v1 = h4_to_f4(__ldg(&h2[(size_t)u1 * 32 + lane]));
        float4 v2 = h4_to_f4(__ldg(&h2[(size_t)u2 * 32 + lane]));
        float4 v3 = h4_to_f4(__ldg(&h2[(size_t)u3 * 32 + lane]));
        acc.x += (v0.x + v1.x) + (v2.x + v3.x);
        acc.y += (v0.y + v1.y) + (v2.y + v3.y);
        acc.z += (v0.z + v1.z) + (v2.z + v3.z);
        acc.w += (v0.w + v1.w) + (v2.w + v3.w);
    }
    for (; i < e; i++) {
        int u = cs[i];
        float4 v = h4_to_f4(__ldg(&h2[(size_t)u * 32 + lane]));
        acc.x += v.x; acc.y += v.y; acc.z += v.z; acc.w += v.w;
    }
    __half2 p01 = __floats2half2_rn(acc.x, acc.y);
    __half2 p23 = __floats2half2_rn(acc.z, acc.w);
    uint2 o;
    o.x = *(uint32_t*)&p01;
    o.y = *(uint32_t*)&p23;
    ((uint2*)asum16)[(size_t)gw * 32 + lane] = o;
}

// ---------------- GEMM tile machinery: 64 rows/CTA, 128 threads (2M x 2N warps), occ 3 -------
#define PITCH 136
#define OFF_AH 0
#define OFF_AL (64 * PITCH * 2)             // 17408
#define OFF_B  (2 * 64 * PITCH * 2)         // 34816
#define SM_TOT (OFF_B + 128 * PITCH * 2)    // 69632 -> 3 CTAs/SM

__device__ __forceinline__ void stage_W(uint32_t sb, const __half* Wfmt, int tid) {
    const float4* src = (const float4*)Wfmt;
#pragma unroll
    for (int i = 0; i < 16; i++) {
        int id = tid + i * 128;             // 2048 float4
        int n = id >> 4, c = id & 15;
        cpasync16(sb + OFF_B + n * (PITCH * 2) + c * 16, src + id);
    }
    asm volatile("cp.async.commit_group;" ::: "memory");
}

__device__ __forceinline__ void mainloop(uint32_t sb, uint32_t aoff0, uint32_t aoff1,
                                         uint32_t boff, float acc[2][8][4]) {
#pragma unroll
    for (int ks = 0; ks < 8; ks++) {
        uint32_t kb = ks * 32;
        uint32_t ah[2][4], al[2][4], b[4][4];
        ldsm4(ah[0], sb + OFF_AH + aoff0 + kb);
        ldsm4(ah[1], sb + OFF_AH + aoff1 + kb);
        ldsm4(al[0], sb + OFF_AL + aoff0 + kb);
        ldsm4(al[1], sb + OFF_AL + aoff1 + kb);
#pragma unroll
        for (int nt = 0; nt < 4; nt++)
            ldsm4(b[nt], sb + OFF_B + boff + nt * 16 * (PITCH * 2) + kb);
#pragma unroll
        for (int mi = 0; mi < 2; mi++)
#pragma unroll
            for (int nt = 0; nt < 4; nt++) {
                MMA_F16(acc[mi][2 * nt],     ah[mi], b[nt][0], b[nt][1]);
                MMA_F16(acc[mi][2 * nt],     al[mi], b[nt][0], b[nt][1]);
                MMA_F16(acc[mi][2 * nt + 1], ah[mi], b[nt][2], b[nt][3]);
                MMA_F16(acc[mi][2 * nt + 1], al[mi], b[nt][2], b[nt][3]);
            }
    }
}

// ---------------- GEMM0: C16 = fp16(relu(x @ W + b)), x fp32 ----------------
__global__ __launch_bounds__(128, 3) void tgemm_kernel(
    const float* __restrict__ A, const __half* __restrict__ Wfmt,
    const float* __restrict__ bias, __half* __restrict__ C16) {
    extern __shared__ char sm[];
    uint32_t sb = smem_u32(sm);
    int tid = threadIdx.x;
    int lane = tid & 31, wid = tid >> 5;
    int bm = blockIdx.x * 64;

    stage_W(sb, Wfmt, tid);
    {
        const float4* Ap = (const float4*)A;
#pragma unroll
        for (int i = 0; i < 16; i++) {
            int id4 = tid + i * 128;
            int m = id4 >> 5, k4 = id4 & 31;
            int gr = bm + m;
            if (gr >= NODES) gr = NODES - 1;
            float4 g = Ap[(size_t)gr * 32 + k4];
            uint2 uh, ul;
            split_f16(g, uh, ul);
            int db = m * (PITCH * 2) + k4 * 8;
            *(uint2*)(sm + OFF_AH + db) = uh;
            *(uint2*)(sm + OFF_AL + db) = ul;
        }
    }
    asm volatile("cp.async.wait_group 0;" ::: "memory");
    __syncthreads();

    int mwarp = wid & 1, nwarp = wid >> 1;
    int m0 = mwarp * 32, n0 = nwarp * 64;
    uint32_t arow = (lane & 7) + ((lane >> 3) & 1) * 8;
    uint32_t acol = (lane >> 4) * 8;
    uint32_t aoff0 = ((m0 + arow) * PITCH + acol) * 2;
    uint32_t aoff1 = ((m0 + 16 + arow) * PITCH + acol) * 2;
    uint32_t boff = ((n0 + (lane & 7) + (lane >> 4) * 8) * PITCH + ((lane >> 3) & 1) * 8) * 2;

    float acc[2][8][4];
#pragma unroll
    for (int mi = 0; mi < 2; mi++)
#pragma unroll
        for (int t = 0; t < 8; t++)
#pragma unroll
            for (int j = 0; j < 4; j++) acc[mi][t][j] = 0.0f;

    mainloop(sb, aoff0, aoff1, boff, acc);

    int c2 = (lane & 3) * 2;
#pragma unroll
    for (int mi = 0; mi < 2; mi++) {
        int r = bm + m0 + mi * 16 + (lane >> 2);
#pragma unroll
        for (int t = 0; t < 8; t++) {
            int col = n0 + t * 8 + c2;
            float2 bv = *(const float2*)(bias + col);
            if (r < NODES) {
                *(__half2*)(C16 + (size_t)r * HD + col) =
                    __floats2half2_rn(fmaxf(acc[mi][t][0] + bv.x, 0.f),
                                      fmaxf(acc[mi][t][1] + bv.y, 0.f));
            }
            if (r + 8 < NODES) {
                *(__half2*)(C16 + (size_t)(r + 8) * HD + col) =
                    __floats2half2_rn(fmaxf(acc[mi][t][2] + bv.x, 0.f),
                                      fmaxf(acc[mi][t][3] + bv.y, 0.f));
            }
        }
    }
}

// ---------------- fused MLP: C16 = fp16(relu(relu(asum16@W1+b1)@W2 + b2 + h0_16)) --------------
__global__ __launch_bounds__(128, 3) void tgemm_fused_kernel(
    const __half* __restrict__ A16,
    const __half* __restrict__ W1f, const float* __restrict__ b1,
    const __half* __restrict__ W2f, const float* __restrict__ b2,
    const __half* __restrict__ res16, __half* __restrict__ C16) {
    extern __shared__ char sm[];
    uint32_t sb = smem_u32(sm);
    int tid = threadIdx.x;
    int lane = tid & 31, wid = tid >> 5;
    int bm = blockIdx.x * 64;

    stage_W(sb, W1f, tid);
    {
        const uint2* Hp = (const uint2*)A16;
#pragma unroll
        for (int i = 0; i < 16; i++) {
            int id4 = tid + i * 128;
            int m = id4 >> 5, k4 = id4 & 31;
            int gr = bm + m;
            if (gr >= NODES) gr = NODES - 1;
            float4 a = h4_to_f4(Hp[(size_t)gr * 32 + k4]);
            uint2 uh, ul;
            split_f16(a, uh, ul);
            int db = m * (PITCH * 2) + k4 * 8;
            *(uint2*)(sm + OFF_AH + db) = uh;
            *(uint2*)(sm + OFF_AL + db) = ul;
        }
    }
    asm volatile("cp.async.wait_group 0;" ::: "memory");
    __syncthreads();

    int mwarp = wid & 1, nwarp = wid >> 1;
    int m0 = mwarp * 32, n0 = nwarp * 64;
    uint32_t arow = (lane & 7) + ((lane >> 3) & 1) * 8;
    uint32_t acol = (lane >> 4) * 8;
    uint32_t aoff0 = ((m0 + arow) * PITCH + acol) * 2;
    uint32_t aoff1 = ((m0 + 16 + arow) * PITCH + acol) * 2;
    uint32_t boff = ((n0 + (lane & 7) + (lane >> 4) * 8) * PITCH + ((lane >> 3) & 1) * 8) * 2;

    float acc[2][8][4];
#pragma unroll
    for (int mi = 0; mi < 2; mi++)
#pragma unroll
        for (int t = 0; t < 8; t++)
#pragma unroll
            for (int j = 0; j < 4; j++) acc[mi][t][j] = 0.0f;

    // ---- GEMM1: t1 = relu(asum @ W1 + b1) ----
    mainloop(sb, aoff0, aoff1, boff, acc);

    __syncthreads();

    stage_W(sb, W2f, tid);   // async, overlaps t1 conversion

    int c2 = (lane & 3) * 2;
#pragma unroll
    for (int mi = 0; mi < 2; mi++) {
        int rl = m0 + mi * 16 + (lane >> 2);
#pragma unroll
        for (int t = 0; t < 8; t++) {
            int col = n0 + t * 8 + c2;
            float2 bv = *(const float2*)(b1 + col);
            float x0 = fmaxf(acc[mi][t][0] + bv.x, 0.f);
            float x1 = fmaxf(acc[mi][t][1] + bv.y, 0.f);
            float y0 = fmaxf(acc[mi][t][2] + bv.x, 0.f);
            float y1 = fmaxf(acc[mi][t][3] + bv.y, 0.f);
            uint32_t hi, lo;
            split_f16_pair(x0, x1, hi, lo);
            *(uint32_t*)(sm + OFF_AH + rl * (PITCH * 2) + col * 2) = hi;
            *(uint32_t*)(sm + OFF_AL + rl * (PITCH * 2) + col * 2) = lo;
            split_f16_pair(y0, y1, hi, lo);
            *(uint32_t*)(sm + OFF_AH + (rl + 8) * (PITCH * 2) + col * 2) = hi;
            *(uint32_t*)(sm + OFF_AL + (rl + 8) * (PITCH * 2) + col * 2) = lo;
        }
    }

#pragma unroll
    for (int mi = 0; mi < 2; mi++)
#pragma unroll
        for (int t = 0; t < 8; t++)
#pragma unroll
            for (int j = 0; j < 4; j++) acc[mi][t][j] = 0.0f;

    asm volatile("cp.async.wait_group 0;" ::: "memory");
    __syncthreads();

    // ---- GEMM2: h = relu(t1 @ W2 + b2 + h0) ----
    mainloop(sb, aoff0, aoff1, boff, acc);

#pragma unroll
    for (int mi = 0; mi < 2; mi++) {
        int r = bm + m0 + mi * 16 + (lane >> 2);
#pragma unroll
        for (int t = 0; t < 8; t++) {
            int col = n0 + t * 8 + c2;
            float2 bv = *(const float2*)(b2 + col);
            if (r < NODES) {
                float2 rv = __half22float2(*(const __half2*)(res16 + (size_t)r * HD + col));
                *(__half2*)(C16 + (size_t)r * HD + col) =
                    __floats2half2_rn(fmaxf(acc[mi][t][0] + bv.x + rv.x, 0.f),
                                      fmaxf(acc[mi][t][1] + bv.y + rv.y, 0.f));
            }
            if (r + 8 < NODES) {
                float2 rv = __half22float2(*(const __half2*)(res16 + (size_t)(r + 8) * HD + col));
                *(__half2*)(C16 + (size_t)(r + 8) * HD + col) =
                    __floats2half2_rn(fmaxf(acc[mi][t][2] + bv.x + rv.x, 0.f),
                                      fmaxf(acc[mi][t][3] + bv.y + rv.y, 0.f));
            }
        }
    }
}

// ---------------- pooling ----------------
__global__ void pool_kernel(const __half* __restrict__ h16, const int* __restrict__ batch,
                            float* __restrict__ pooled) {
    const int CH = 64;
    int t = threadIdx.x;
    int n0 = blockIdx.x * CH;
    int n1 = n0 + CH;
    if (n1 > NODES) n1 = NODES;
    float acc = 0.0f;
    int cur = batch[n0];
    for (int n = n0; n < n1; n++) {
        int g = batch[n];
        if (g != cur) {
            atomicAdd(&pooled[cur * HD + t], acc);
            acc = 0.0f;
            cur = g;
        }
        acc += __half2float(h16[(size_t)n * HD + t]);
    }
    atomicAdd(&pooled[cur * HD + t], acc);
}
__global__ void final_kernel(const float* __restrict__ pooled, const float* __restrict__ Wf,
                             const float* __restrict__ bf, float* __restrict__ out) {
    int g = blockIdx.x, t = threadIdx.x;
    __shared__ float sm[128];
    sm[t] = pooled[g * HD + t] * Wf[t];
    __syncthreads();
#pragma unroll
    for (int o = 64; o > 0; o >>= 1) {
        if (t < o) sm[t] += sm[t + o];
        __syncthreads();
    }
    if (t == 0) out[g] = sm[0] + bf[0];
}

// ---------------- launch ----------------
extern "C" void kernel_launch(void* const* d_in, const int* in_sizes, int n_in,
                              void* d_out, int out_size) {
    const float* x  = (const float*)d_in[0];
    const int* ei   = (const int*)d_in[1];
    const int* batch = (const int*)d_in[3];
    const float* W0 = (const float*)d_in[4];
    const float* b0 = (const float*)d_in[5];
    const float* W1 = (const float*)d_in[6];
    const float* b1 = (const float*)d_in[7];
    const float* W2 = (const float*)d_in[8];
    const float* b2 = (const float*)d_in[9];
    const float* Wf = (const float*)d_in[10];
    const float* bf = (const float*)d_in[11];
    float* out = (float*)d_out;
    int E = in_sizes[1] / 2;

    cudaFuncSetAttribute(tgemm_kernel, cudaFuncAttributeMaxDynamicSharedMemorySize, SM_TOT);
    cudaFuncSetAttribute(tgemm_fused_kernel, cudaFuncAttributeMaxDynamicSharedMemorySize, SM_TOT);

    float *pooled;
    __half *h0x, *hx, *asum, *wfmt;
    int *rowptr, *cursor, *csr, *bsums;
    cudaGetSymbolAddress((void**)&h0x, g_h0x);
    cudaGetSymbolAddress((void**)&hx, g_hx);
    cudaGetSymbolAddress((void**)&asum, g_asum);
    cudaGetSymbolAddress((void**)&pooled, g_pooled);
    cudaGetSymbolAddress((void**)&rowptr, g_rowptr);
    cudaGetSymbolAddress((void**)&cursor, g_cursor);
    cudaGetSymbolAddress((void**)&csr, g_csr);
    cudaGetSymbolAddress((void**)&bsums, g_bsums);
    cudaGetSymbolAddress((void**)&wfmt, g_wfmt);

    int nb = (NODES + 255) / 256;

    wfmt_kernel<<<dim3(9, 16), 256>>>(W0, W1, W2, wfmt);

    zero_int_kernel<<<(NODES + 1 + 255) / 256, 256>>>(rowptr, NODES + 1);
    hist_kernel<<<(E + 255) / 256, 256>>>(ei, rowptr, E);
    scan_blocks_kernel<<<nb, 256>>>(rowptr, bsums, NODES);
    scan_bsums_kernel<<<1, 512>>>(bsums, nb);
    scan_finish_kernel<<<nb, 256>>>(rowptr, bsums, cursor, NODES, E);
    fill_csr_kernel<<<(E + 255) / 256, 256>>>(ei, cursor, csr, E);

    int gg = (NODES + 63) / 64;  // 1563

    // h0 = fp16(relu(x @ W0 + b0))
    tgemm_kernel<<<gg, 128, SM_TOT>>>(x, wfmt, b0, h0x);

    for (int i = 0; i < 4; i++) {
        const __half* hcur = (i == 0) ? h0x : hx;
        agg_kernel<<<(NODES * 32 + 255) / 256, 256>>>(rowptr, csr, hcur, asum);
        tgemm_fused_kernel<<<gg, 128, SM_TOT>>>(asum,
                                                wfmt + (size_t)(1 + i) * 16384, b1 + i * HD,
                                                wfmt + (size_t)(5 + i) * 16384, b2 + i * HD,
                                                h0x, hx);
    }

    zero_float_kernel<<<(NGR * HD + 255) / 256, 256>>>(pooled, NGR * HD);
    pool_kernel<<<(NODES + 63) / 64, 128>>>(hx, batch, pooled);
    final_kernel<<<NGR, 128>>>(pooled, Wf, bf, out);
}

// round 16
// speedup vs baseline: 1.2092x; 1.1683x over previous
#include <cuda_runtime.h>
#include <cuda_fp16.h>
#include <cstdint>

#define NODES 100000
#define NGR   1000
#define HD    128
#define NEDGE 1600000

// ---------------- scratch (activations fp16; fp32 accumulate) ----------------
__device__ __half g_h0x[NODES * HD];    // h0 fp16
__device__ __half g_hx[NODES * HD];     // current h fp16
__device__ __half g_asum[NODES * HD];   // self + neighbor sum, fp16
__device__ float g_pooled[NGR * HD];
__device__ int   g_rowptr[NODES + 1];
__device__ int   g_cursor[NODES];
__device__ int   g_csr[NEDGE];
__device__ int   g_bsums[512];
__device__ __half g_wfmt[9 * 16384];    // 9 mats x Wt[n][k] fp16

// ---------------- ptx helpers ----------------
__device__ __forceinline__ uint32_t smem_u32(const void* p) {
    uint32_t a;
    asm("{ .reg .u64 t; cvta.to.shared.u64 t, %1; cvt.u32.u64 %0, t; }" : "=r"(a) : "l"(p));
    return a;
}
__device__ __forceinline__ void ldsm4(uint32_t* r, uint32_t a) {
    asm volatile("ldmatrix.sync.aligned.m8n8.x4.shared.b16 {%0,%1,%2,%3}, [%4];"
                 : "=r"(r[0]), "=r"(r[1]), "=r"(r[2]), "=r"(r[3]) : "r"(a));
}
__device__ __forceinline__ void cpasync16(uint32_t dst, const void* src) {
    asm volatile("cp.async.cg.shared.global [%0], [%1], 16;" :: "r"(dst), "l"(src));
}
#define MMA_F16(ac, af, b0, b1)                                                     \
    asm volatile(                                                                   \
        "mma.sync.aligned.m16n8k16.row.col.f32.f16.f16.f32 "                        \
        "{%0,%1,%2,%3}, {%4,%5,%6,%7}, {%8,%9}, {%0,%1,%2,%3};"                     \
        : "+f"((ac)[0]), "+f"((ac)[1]), "+f"((ac)[2]), "+f"((ac)[3])                \
        : "r"((af)[0]), "r"((af)[1]), "r"((af)[2]), "r"((af)[3]), "r"(b0), "r"(b1))

// single fp16 rounding of a float4 (A operand)
__device__ __forceinline__ uint2 pack_f16(float4 g) {
    __half2 h01 = __floats2half2_rn(g.x, g.y);
    __half2 h23 = __floats2half2_rn(g.z, g.w);
    uint2 u;
    u.x = *(uint32_t*)&h01;
    u.y = *(uint32_t*)&h23;
    return u;
}
__device__ __forceinline__ float4 h4_to_f4(uint2 v) {
    float2 fa = __half22float2(*(__half2*)&v.x);
    float2 fb = __half22float2(*(__half2*)&v.y);
    return make_float4(fa.x, fa.y, fb.x, fb.y);
}

// ---------------- weight pre-format ----------------
__global__ void wfmt_kernel(const float* __restrict__ W0, const float* __restrict__ W1,
                            const float* __restrict__ W2, __half* __restrict__ out) {
    int mat = blockIdx.x;
    int chunk = blockIdx.y;
    const float* W = (mat == 0) ? W0 : (mat <= 4 ? W1 + (mat - 1) * HD * HD
                                                 : W2 + (mat - 5) * HD * HD);
    __half* o = out + (size_t)mat * 16384;
    int base = chunk * 1024;
    for (int i = threadIdx.x; i < 1024; i += blockDim.x) {
        int id = base + i;
        int k = id >> 7, n = id & 127;
        o[n * HD + k] = __float2half(W[id]);
    }
}

// ---------------- utility ----------------
__global__ void zero_int_kernel(int* p, int n) {
    int i = blockIdx.x * blockDim.x + threadIdx.x;
    if (i < n) p[i] = 0;
}
__global__ void zero_float_kernel(float* p, int n) {
    int i = blockIdx.x * blockDim.x + threadIdx.x;
    if (i < n) p[i] = 0.0f;
}

// ---------------- CSR build ----------------
__global__ void hist_kernel(const int* __restrict__ ei, int* __restrict__ deg, int E) {
    int e = blockIdx.x * blockDim.x + threadIdx.x;
    if (e < E) atomicAdd(&deg[ei[E + e]], 1);
}
__global__ void scan_blocks_kernel(int* __restrict__ data, int* __restrict__ bsums, int n) {
    int tid = threadIdx.x;
    int i = blockIdx.x * 256 + tid;
    int v = (i < n) ? data[i] : 0;
    int x = v;
#pragma unroll
    for (int o = 1; o < 32; o <<= 1) {
        int y = __shfl_up_sync(0xffffffffu, x, o);
        if ((tid & 31) >= o) x += y;
    }
    __shared__ int ws[8];
    if ((tid & 31) == 31) ws[tid >> 5] = x;
    __syncthreads();
    if (tid == 0) {
        int run = 0;
#pragma unroll
        for (int w = 0; w < 8; w++) { int t = ws[w]; ws[w] = run; run += t; }
    }
    __syncthreads();
    int incl = x + ws[tid >> 5];
    if (i < n) data[i] = incl - v;
    if (tid == 255) bsums[blockIdx.x] = incl;
}
__global__ void scan_bsums_kernel(int* bsums, int nb) {
    int tid = threadIdx.x;
    int v = (tid < nb) ? bsums[tid] : 0;
    int x = v;
#pragma unroll
    for (int o = 1; o < 32; o <<= 1) {
        int y = __shfl_up_sync(0xffffffffu, x, o);
        if ((tid & 31) >= o) x += y;
    }
    __shared__ int ws[16];
    if ((tid & 31) == 31) ws[tid >> 5] = x;
    __syncthreads();
    if (tid == 0) {
        int run = 0;
#pragma unroll
        for (int w = 0; w < 16; w++) { int t = ws[w]; ws[w] = run; run += t; }
    }
    __syncthreads();
    int incl = x + ws[tid >> 5];
    if (tid < nb) bsums[tid] = incl - v;
}
__global__ void scan_finish_kernel(int* __restrict__ rowptr, const int* __restrict__ bsums,
                                   int* __restrict__ cursor, int n, int E) {
    int i = blockIdx.x * 256 + threadIdx.x;
    if (i < n) {
        int v = rowptr[i] + bsums[blockIdx.x];
        rowptr[i] = v;
        cursor[i] = v;
    }
    if (i == 0) rowptr[n] = E;
}
__global__ void fill_csr_kernel(const int* __restrict__ ei, int* __restrict__ cursor,
                                int* __restrict__ csr, int E) {
    int e = blockIdx.x * blockDim.x + threadIdx.x;
    if (e < E) {
        int s = ei[e];
        int d = ei[E + e];
        int p = atomicAdd(&cursor[d], 1);
        csr[p] = s;
    }
}

// ---------------- aggregation: asum = h[node] + sum_j h[j]  (fp32 acc, fp16 out) --------------
__global__ void agg_kernel(const int* __restrict__ rp, const int* __restrict__ cs,
                           const __half* __restrict__ h16, __half* __restrict__ asum16) {
    int gw = (blockIdx.x * blockDim.x + threadIdx.x) >> 5;
    int lane = threadIdx.x & 31;
    if (gw >= NODES) return;
    int s = rp[gw], e = rp[gw + 1];
    const uint2* h2 = (const uint2*)h16;
    float4 acc = h4_to_f4(__ldg(&h2[(size_t)gw * 32 + lane]));   // self term
    int i = s;
    for (; i + 3 < e; i += 4) {
        int u0 = cs[i], u1 = cs[i + 1], u2 = cs[i + 2], u3 = cs[i + 3];
        float4 v0 = h4_to_f4(__ldg(&h2[(size_t)u0 * 32 + lane]));
        float4 v1 = h4_to_f4(__ldg(&h2[(size_t)u1 * 32 + lane]));
        float4 v2 = h4_to_f4(__ldg(&h2[(size_t)u2 * 32 + lane]));
        float4 v3 = h4_to_f4(__ldg(&h2[(size_t)u3 * 32 + lane]));
        acc.x += (v0.x + v1.x) + (v2.x + v3.x);
        acc.y += (v0.y + v1.y) + (v2.y + v3.y);
        acc.z += (v0.z + v1.z) + (v2.z + v3.z);
        acc.w += (v0.w + v1.w) + (v2.w + v3.w);
    }
    for (; i < e; i++) {
        int u = cs[i];
        float4 v = h4_to_f4(__ldg(&h2[(size_t)u * 32 + lane]));
        acc.x += v.x; acc.y += v.y; acc.z += v.z; acc.w += v.w;
    }
    ((uint2*)asum16)[(size_t)gw * 32 + lane] = pack_f16(acc);
}

// ---------------- GEMM tile machinery: 64 rows/CTA, 128 threads, single A product, occ 4 -----
#define PITCH 136
#define OFF_A  0
#define OFF_B  (64 * PITCH * 2)             // 17408
#define SM_TOT (OFF_B + 128 * PITCH * 2)    // 52224 -> 4 CTAs/SM

__device__ __forceinline__ void stage_W(uint32_t sb, const __half* Wfmt, int tid) {
    const float4* src = (const float4*)Wfmt;
#pragma unroll
    for (int i = 0; i < 16; i++) {
        int id = tid + i * 128;             // 2048 float4
        int n = id >> 4, c = id & 15;
        cpasync16(sb + OFF_B + n * (PITCH * 2) + c * 16, src + id);
    }
    asm volatile("cp.async.commit_group;" ::: "memory");
}

// full K=128 mainloop, single fp16 A product
__device__ __forceinline__ void mainloop(uint32_t sb, uint32_t aoff0, uint32_t aoff1,
                                         uint32_t boff, float acc[2][8][4]) {
#pragma unroll
    for (int ks = 0; ks < 8; ks++) {
        uint32_t kb = ks * 32;
        uint32_t a[2][4], b[4][4];
        ldsm4(a[0], sb + OFF_A + aoff0 + kb);
        ldsm4(a[1], sb + OFF_A + aoff1 + kb);
#pragma unroll
        for (int nt = 0; nt < 4; nt++)
            ldsm4(b[nt], sb + OFF_B + boff + nt * 16 * (PITCH * 2) + kb);
#pragma unroll
        for (int mi = 0; mi < 2; mi++)
#pragma unroll
            for (int nt = 0; nt < 4; nt++) {
                MMA_F16(acc[mi][2 * nt],     a[mi], b[nt][0], b[nt][1]);
                MMA_F16(acc[mi][2 * nt + 1], a[mi], b[nt][2], b[nt][3]);
            }
    }
}

// ---------------- GEMM0: C16 = fp16(relu(x @ W + b)), x fp32 -> fp16 once ----------------
__global__ __launch_bounds__(128, 4) void tgemm_kernel(
    const float* __restrict__ A, const __half* __restrict__ Wfmt,
    const float* __restrict__ bias, __half* __restrict__ C16) {
    extern __shared__ char sm[];
    uint32_t sb = smem_u32(sm);
    int tid = threadIdx.x;
    int lane = tid & 31, wid = tid >> 5;
    int bm = blockIdx.x * 64;

    stage_W(sb, Wfmt, tid);
    {
        const float4* Ap = (const float4*)A;
#pragma unroll
        for (int i = 0; i < 16; i++) {
            int id4 = tid + i * 128;
            int m = id4 >> 5, k4 = id4 & 31;
            int gr = bm + m;
            if (gr >= NODES) gr = NODES - 1;
            float4 g = Ap[(size_t)gr * 32 + k4];
            *(uint2*)(sm + OFF_A + m * (PITCH * 2) + k4 * 8) = pack_f16(g);
        }
    }
    asm volatile("cp.async.wait_group 0;" ::: "memory");
    __syncthreads();

    int mwarp = wid & 1, nwarp = wid >> 1;
    int m0 = mwarp * 32, n0 = nwarp * 64;
    uint32_t arow = (lane & 7) + ((lane >> 3) & 1) * 8;
    uint32_t acol = (lane >> 4) * 8;
    uint32_t aoff0 = ((m0 + arow) * PITCH + acol) * 2;
    uint32_t aoff1 = ((m0 + 16 + arow) * PITCH + acol) * 2;
    uint32_t boff = ((n0 + (lane & 7) + (lane >> 4) * 8) * PITCH + ((lane >> 3) & 1) * 8) * 2;

    float acc[2][8][4];
#pragma unroll
    for (int mi = 0; mi < 2; mi++)
#pragma unroll
        for (int t = 0; t < 8; t++)
#pragma unroll
            for (int j = 0; j < 4; j++) acc[mi][t][j] = 0.0f;

    mainloop(sb, aoff0, aoff1, boff, acc);

    int c2 = (lane & 3) * 2;
#pragma unroll
    for (int mi = 0; mi < 2; mi++) {
        int r = bm + m0 + mi * 16 + (lane >> 2);
#pragma unroll
        for (int t = 0; t < 8; t++) {
            int col = n0 + t * 8 + c2;
            float2 bv = *(const float2*)(bias + col);
            if (r < NODES) {
                *(__half2*)(C16 + (size_t)r * HD + col) =
                    __floats2half2_rn(fmaxf(acc[mi][t][0] + bv.x, 0.f),
                                      fmaxf(acc[mi][t][1] + bv.y, 0.f));
            }
            if (r + 8 < NODES) {
                *(__half2*)(C16 + (size_t)(r + 8) * HD + col) =
                    __floats2half2_rn(fmaxf(acc[mi][t][2] + bv.x, 0.f),
                                      fmaxf(acc[mi][t][3] + bv.y, 0.f));
            }
        }
    }
}

// ---------------- fused MLP: C16 = fp16(relu(relu(asum16@W1+b1)@W2 + b2 + h0_16)) --------------
__global__ __launch_bounds__(128, 4) void tgemm_fused_kernel(
    const __half* __restrict__ A16,
    const __half* __restrict__ W1f, const float* __restrict__ b1,
    const __half* __restrict__ W2f, const float* __restrict__ b2,
    const __half* __restrict__ res16, __half* __restrict__ C16) {
    extern __shared__ char sm[];
    uint32_t sb = smem_u32(sm);
    int tid = threadIdx.x;
    int lane = tid & 31, wid = tid >> 5;
    int bm = blockIdx.x * 64;

    stage_W(sb, W1f, tid);
    {
        // A16 already fp16: raw 16B copies into smem (no convert, no split)
        const uint2* Hp = (const uint2*)A16;
#pragma unroll
        for (int i = 0; i < 16; i++) {
            int id4 = tid + i * 128;
            int m = id4 >> 5, k4 = id4 & 31;
            int gr = bm + m;
            if (gr >= NODES) gr = NODES - 1;
            *(uint2*)(sm + OFF_A + m * (PITCH * 2) + k4 * 8) = Hp[(size_t)gr * 32 + k4];
        }
    }
    asm volatile("cp.async.wait_group 0;" ::: "memory");
    __syncthreads();

    int mwarp = wid & 1, nwarp = wid >> 1;
    int m0 = mwarp * 32, n0 = nwarp * 64;
    uint32_t arow = (lane & 7) + ((lane >> 3) & 1) * 8;
    uint32_t acol = (lane >> 4) * 8;
    uint32_t aoff0 = ((m0 + arow) * PITCH + acol) * 2;
    uint32_t aoff1 = ((m0 + 16 + arow) * PITCH + acol) * 2;
    uint32_t boff = ((n0 + (lane & 7) + (lane >> 4) * 8) * PITCH + ((lane >> 3) & 1) * 8) * 2;

    float acc[2][8][4];
#pragma unroll
    for (int mi = 0; mi < 2; mi++)
#pragma unroll
        for (int t = 0; t < 8; t++)
#pragma unroll
            for (int j = 0; j < 4; j++) acc[mi][t][j] = 0.0f;

    // ---- GEMM1: t1 = relu(asum @ W1 + b1) ----
    mainloop(sb, aoff0, aoff1, boff, acc);

    __syncthreads();

    stage_W(sb, W2f, tid);   // async, overlaps t1 conversion

    int c2 = (lane & 3) * 2;
#pragma unroll
    for (int mi = 0; mi < 2; mi++) {
        int rl = m0 + mi * 16 + (lane >> 2);
#pragma unroll
        for (int t = 0; t < 8; t++) {
            int col = n0 + t * 8 + c2;
            float2 bv = *(const float2*)(b1 + col);
            __half2 hx0 = __floats2half2_rn(fmaxf(acc[mi][t][0] + bv.x, 0.f),
                                            fmaxf(acc[mi][t][1] + bv.y, 0.f));
            __half2 hy0 = __floats2half2_rn(fmaxf(acc[mi][t][2] + bv.x, 0.f),
                                            fmaxf(acc[mi][t][3] + bv.y, 0.f));
            *(uint32_t*)(sm + OFF_A + rl * (PITCH * 2) + col * 2) = *(uint32_t*)&hx0;
            *(uint32_t*)(sm + OFF_A + (rl + 8) * (PITCH * 2) + col * 2) = *(uint32_t*)&hy0;
        }
    }

#pragma unroll
    for (int mi = 0; mi < 2; mi++)
#pragma unroll
        for (int t = 0; t < 8; t++)
#pragma unroll
            for (int j = 0; j < 4; j++) acc[mi][t][j] = 0.0f;

    asm volatile("cp.async.wait_group 0;" ::: "memory");
    __syncthreads();

    // ---- GEMM2: h = relu(t1 @ W2 + b2 + h0) ----
    mainloop(sb, aoff0, aoff1, boff, acc);

#pragma unroll
    for (int mi = 0; mi < 2; mi++) {
        int r = bm + m0 + mi * 16 + (lane >> 2);
#pragma unroll
        for (int t = 0; t < 8; t++) {
            int col = n0 + t * 8 + c2;
            float2 bv = *(const float2*)(b2 + col);
            if (r < NODES) {
                float2 rv = __half22float2(*(const __half2*)(res16 + (size_t)r * HD + col));
                *(__half2*)(C16 + (size_t)r * HD + col) =
                    __floats2half2_rn(fmaxf(acc[mi][t][0] + bv.x + rv.x, 0.f),
                                      fmaxf(acc[mi][t][1] + bv.y + rv.y, 0.f));
            }
            if (r + 8 < NODES) {
                float2 rv = __half22float2(*(const __half2*)(res16 + (size_t)(r + 8) * HD + col));
                *(__half2*)(C16 + (size_t)(r + 8) * HD + col) =
                    __floats2half2_rn(fmaxf(acc[mi][t][2] + bv.x + rv.x, 0.f),
                                      fmaxf(acc[mi][t][3] + bv.y + rv.y, 0.f));
            }
        }
    }
}

// ---------------- pooling ----------------
__global__ void pool_kernel(const __half* __restrict__ h16, const int* __restrict__ batch,
                            float* __restrict__ pooled) {
    const int CH = 64;
    int t = threadIdx.x;
    int n0 = blockIdx.x * CH;
    int n1 = n0 + CH;
    if (n1 > NODES) n1 = NODES;
    float acc = 0.0f;
    int cur = batch[n0];
    for (int n = n0; n < n1; n++) {
        int g = batch[n];
        if (g != cur) {
            atomicAdd(&pooled[cur * HD + t], acc);
            acc = 0.0f;
            cur = g;
        }
        acc += __half2float(h16[(size_t)n * HD + t]);
    }
    atomicAdd(&pooled[cur * HD + t], acc);
}
__global__ void final_kernel(const float* __restrict__ pooled, const float* __restrict__ Wf,
                             const float* __restrict__ bf, float* __restrict__ out) {
    int g = blockIdx.x, t = threadIdx.x;
    __shared__ float sm[128];
    sm[t] = pooled[g * HD + t] * Wf[t];
    __syncthreads();
#pragma unroll
    for (int o = 64; o > 0; o >>= 1) {
        if (t < o) sm[t] += sm[t + o];
        __syncthreads();
    }
    if (t == 0) out[g] = sm[0] + bf[0];
}

// ---------------- launch ----------------
extern "C" void kernel_launch(void* const* d_in, const int* in_sizes, int n_in,
                              void* d_out, int out_size) {
    const float* x  = (const float*)d_in[0];
    const int* ei   = (const int*)d_in[1];
    const int* batch = (const int*)d_in[3];
    const float* W0 = (const float*)d_in[4];
    const float* b0 = (const float*)d_in[5];
    const float* W1 = (const float*)d_in[6];
    const float* b1 = (const float*)d_in[7];
    const float* W2 = (const float*)d_in[8];
    const float* b2 = (const float*)d_in[9];
    const float* Wf = (const float*)d_in[10];
    const float* bf = (const float*)d_in[11];
    float* out = (float*)d_out;
    int E = in_sizes[1] / 2;

    cudaFuncSetAttribute(tgemm_kernel, cudaFuncAttributeMaxDynamicSharedMemorySize, SM_TOT);
    cudaFuncSetAttribute(tgemm_fused_kernel, cudaFuncAttributeMaxDynamicSharedMemorySize, SM_TOT);

    float *pooled;
    __half *h0x, *hx, *asum, *wfmt;
    int *rowptr, *cursor, *csr, *bsums;
    cudaGetSymbolAddress((void**)&h0x, g_h0x);
    cudaGetSymbolAddress((void**)&hx, g_hx);
    cudaGetSymbolAddress((void**)&asum, g_asum);
    cudaGetSymbolAddress((void**)&pooled, g_pooled);
    cudaGetSymbolAddress((void**)&rowptr, g_rowptr);
    cudaGetSymbolAddress((void**)&cursor, g_cursor);
    cudaGetSymbolAddress((void**)&csr, g_csr);
    cudaGetSymbolAddress((void**)&bsums, g_bsums);
    cudaGetSymbolAddress((void**)&wfmt, g_wfmt);

    int nb = (NODES + 255) / 256;

    wfmt_kernel<<<dim3(9, 16), 256>>>(W0, W1, W2, wfmt);

    zero_int_kernel<<<(NODES + 1 + 255) / 256, 256>>>(rowptr, NODES + 1);
    hist_kernel<<<(E + 255) / 256, 256>>>(ei, rowptr, E);
    scan_blocks_kernel<<<nb, 256>>>(rowptr, bsums, NODES);
    scan_bsums_kernel<<<1, 512>>>(bsums, nb);
    scan_finish_kernel<<<nb, 256>>>(rowptr, bsums, cursor, NODES, E);
    fill_csr_kernel<<<(E + 255) / 256, 256>>>(ei, cursor, csr, E);

    int gg = (NODES + 63) / 64;  // 1563

    // h0 = fp16(relu(x @ W0 + b0))
    tgemm_kernel<<<gg, 128, SM_TOT>>>(x, wfmt, b0, h0x);

    for (int i = 0; i < 4; i++) {
        const __half* hcur = (i == 0) ? h0x : hx;
        agg_kernel<<<(NODES * 32 + 255) / 256, 256>>>(rowptr, csr, hcur, asum);
        tgemm_fused_kernel<<<gg, 128, SM_TOT>>>(asum,
                                                wfmt + (size_t)(1 + i) * 16384, b1 + i * HD,
                                                wfmt + (size_t)(5 + i) * 16384, b2 + i * HD,
                                                h0x, hx);
    }

    zero_float_kernel<<<(NGR * HD + 255) / 256, 256>>>(pooled, NGR * HD);
    pool_kernel<<<(NODES + 63) / 64, 128>>>(hx, batch, pooled);
    final_kernel<<<NGR, 128>>>(pooled, Wf, bf, out);
}